// round 13
// baseline (speedup 1.0000x reference)
#include <cuda_runtime.h>
#include <cuda_fp16.h>

// FreqGrid triplane encoder. R13 = R12 + MUFU offload:
//  The gather kernel is MUFU-bound (24 __cosf/pt = ~47us pipe floor, measured
//  49.7us). Move 6 of 24 cosines (freq pair q=3 in each plane) to a fp32
//  polynomial on the FMA pipe (which has ~50% headroom).
//  Everything else identical to R12 (best: 70.1us).

#define RR 256
#define CHN 128
#define PLANE_ELEMS (RR * RR)              // 65536
#define GT_ELEMS (3 * PLANE_ELEMS * CHN)   // 48 MB of halfs
#define GT_PAD (33024)                     // covers +row+texel overrun (zeroed)

__device__ __half g_grid_t[GT_ELEMS + GT_PAD];

#define PI_OVER_R 0.01227184630308513f     // pi/256
#define KC        0.006135923151542565f    // pi/512

// swizzled half-index for (spatial row s, channel ch) in a 64x128 tile
__device__ __forceinline__ int sw_idx(int s, int ch) {
    int chunk = (ch >> 3) ^ ((s >> 2) & 15);
    return s * 128 + (chunk << 3) + (ch & 7);
}

// ---------------------------------------------------------------------------
// Transpose + quantize: in[p][ch][s] -> g_grid_t[p][s][ch] (fp16)
// ---------------------------------------------------------------------------
__global__ void __launch_bounds__(256) transpose_kernel(const float* __restrict__ g) {
    __shared__ __half tile[64 * 128];
    const int p  = blockIdx.y;
    const int s0 = blockIdx.x << 6;
    const int tid = threadIdx.x;

    const float* in = g + (size_t)p * CHN * PLANE_ELEMS + s0;

    #pragma unroll
    for (int i = 0; i < 8; i++) {
        int u  = i * 256 + tid;
        int q  = u & 15;
        int ch = u >> 4;
        float4 f = __ldcs((const float4*)(in + (size_t)ch * PLANE_ELEMS + 4 * q));
        tile[sw_idx(4 * q + 0, ch)] = __float2half_rn(f.x);
        tile[sw_idx(4 * q + 1, ch)] = __float2half_rn(f.y);
        tile[sw_idx(4 * q + 2, ch)] = __float2half_rn(f.z);
        tile[sw_idx(4 * q + 3, ch)] = __float2half_rn(f.w);
    }
    __syncthreads();

    __half* outp = g_grid_t + (size_t)p * PLANE_ELEMS * CHN + (size_t)s0 * CHN;
    #pragma unroll
    for (int i = 0; i < 4; i++) {
        int u  = i * 256 + tid;
        int c8 = u & 15;
        int s  = u >> 4;
        int chunk = c8 ^ ((s >> 2) & 15);
        uint4 val = *(const uint4*)&tile[s * 128 + (chunk << 3)];
        *(uint4*)(outp + s * CHN + 8 * c8) = val;
    }
}

// ---------------------------------------------------------------------------
// Full-range fp32 cosine on the FMA pipe (no MUFU).
// cos(x) = P(r^2), r = x/2pi - rint(x/2pi) in [-0.5,0.5].
// Degree-7 even Taylor of cos(2*pi*r): max abs err ~4e-6.
// ---------------------------------------------------------------------------
__device__ __forceinline__ float cos_poly(float x) {
    float t = x * 0.15915494309189535f;     // x / (2*pi)
    t = t - rintf(t);                       // [-0.5, 0.5]  (FRND: alu pipe)
    float u = t * t;
    float p = -1.7143907f;
    p = fmaf(p, u, 7.9013580f);
    p = fmaf(p, u, -26.4262568f);
    p = fmaf(p, u, 60.2446414f);
    p = fmaf(p, u, -85.4568172f);
    p = fmaf(p, u, 64.9393940f);
    p = fmaf(p, u, -19.7392088f);
    p = fmaf(p, u, 1.0f);
    return p;
}

// ---------------------------------------------------------------------------
// Gather + basis: half-warp per point, lane owns output channel c = lane&15
// ---------------------------------------------------------------------------
__device__ __forceinline__ void load_corners(const uint4* __restrict__ gb,
                                             int off, uint4* v) {
    v[0] = __ldg(&gb[off]);
    v[1] = __ldg(&gb[off + 16]);       // +x texel
    v[2] = __ldg(&gb[off + 4096]);     // +y row
    v[3] = __ldg(&gb[off + 4112]);
}

__device__ __forceinline__ void blend_plane(const uint4* v, float wxd, float wyd,
                                            float kdd, const float* frh,
                                            float& acc0, float& acc1) {
    __half2 w00 = __float2half2_rn((1.0f - wxd) * (1.0f - wyd));
    __half2 w01 = __float2half2_rn(wxd * (1.0f - wyd));
    __half2 w10 = __float2half2_rn((1.0f - wxd) * wyd);
    __half2 w11 = __float2half2_rn(wxd * wyd);

    const __half2* c0 = (const __half2*)&v[0];
    const __half2* c1 = (const __half2*)&v[1];
    const __half2* c2 = (const __half2*)&v[2];
    const __half2* c3 = (const __half2*)&v[3];

    #pragma unroll
    for (int q = 0; q < 4; q++) {
        __half2 cf = __hmul2(w00, c0[q]);
        cf = __hfma2(w01, c1[q], cf);
        cf = __hfma2(w10, c2[q], cf);
        cf = __hfma2(w11, c3[q], cf);
        float2 f = __half22float2(cf);
        if (q == 3) {
            // offload this freq pair to the FMA pipe (MUFU is the bottleneck)
            acc0 = fmaf(f.x, cos_poly(kdd * frh[2 * q]),     acc0);
            acc1 = fmaf(f.y, cos_poly(kdd * frh[2 * q + 1]), acc1);
        } else {
            acc0 = fmaf(f.x, __cosf(kdd * frh[2 * q]),     acc0);
            acc1 = fmaf(f.y, __cosf(kdd * frh[2 * q + 1]), acc1);
        }
    }
}

template <int PAIRS>
__global__ void __launch_bounds__(256)
freqgrid_kernel(const float* __restrict__ coords,
                const float* __restrict__ freqs,
                float* __restrict__ out, int N) {
    const int warp = (blockIdx.x * blockDim.x + threadIdx.x) >> 5;
    const int lane = threadIdx.x & 31;
    const int sub  = lane >> 4;     // 0: point A, 1: point B
    const int cl   = lane & 15;     // output channel / uint4 slot

    // Per-lane frequency constants for channels 8*cl + j
    float frh[8];
    #pragma unroll
    for (int j = 0; j < 8; j++) {
        float fq = __ldg(&freqs[8 * cl + j]);
        fq = fminf(fmaxf(fq, 0.0f), 1.0f);
        frh[j] = exp2f(fq * 8.0f) - 0.5f;
    }

    const uint4* __restrict__ gb = (const uint4*)g_grid_t;   // texel = 16 uint4

    const int base0 = warp * (2 * PAIRS);
    #pragma unroll
    for (int t = 0; t < PAIRS; t++) {
        const int nb = base0 + 2 * t;
        if (nb >= N) return;
        const int n = min(nb + sub, N - 1);

        float pt0 = fmaf(__ldcs(&coords[3 * n + 0]), 127.5f, 127.5f);
        float pt1 = fmaf(__ldcs(&coords[3 * n + 1]), 127.5f, 127.5f);
        float pt2 = fmaf(__ldcs(&coords[3 * n + 2]), 127.5f, 127.5f);

        float kd0 = fmaf(pt0, PI_OVER_R, KC);
        float kd1 = fmaf(pt1, PI_OVER_R, KC);
        float kd2 = fmaf(pt2, PI_OVER_R, KC);

        // plane d samples (ix,iy) from pt[{1,0,0}], pt[{2,2,1}]
        // coords in [-1,1): top-edge corners carry exactly-zero weights;
        // padded grid makes the unclamped reads safe.
        int x0a = (int)pt1, y0a = (int)pt2;        // plane 0
        int x0b = (int)pt0, y0b = (int)pt2;        // plane 1
        int x0c = (int)pt0, y0c = (int)pt1;        // plane 2

        float wxa = pt1 - (float)x0a, wya = pt2 - (float)y0a;
        float wxb = pt0 - (float)x0b, wyb = pt2 - (float)y0b;
        float wxc = pt0 - (float)x0c, wyc = pt1 - (float)y0c;

        int offa = (((y0a << 8) + x0a) << 4) + cl;
        int offb = ((PLANE_ELEMS + (y0b << 8) + x0b) << 4) + cl;
        int offc = ((2 * PLANE_ELEMS + (y0c << 8) + x0c) << 4) + cl;

        float acc0 = 0.0f, acc1 = 0.0f;
        uint4 va[4], vb[4];

        // 2-deep software pipeline over the 3 planes
        load_corners(gb, offa, va);
        load_corners(gb, offb, vb);
        blend_plane(va, wxa, wya, kd0, frh, acc0, acc1);
        load_corners(gb, offc, va);
        blend_plane(vb, wxb, wyb, kd1, frh, acc0, acc1);
        blend_plane(va, wxc, wyc, kd2, frh, acc0, acc1);

        if (nb + sub < N) {
            __stcs(&out[n * 16 + cl], 2.0f * (acc0 + acc1));
        }
    }
}

// ---------------------------------------------------------------------------
// Harness entry
// ---------------------------------------------------------------------------
extern "C" void kernel_launch(void* const* d_in, const int* in_sizes, int n_in,
                              void* d_out, int out_size) {
    const float* coords = (const float*)d_in[0];
    const float* grid   = (const float*)d_in[1];
    const float* freqs  = (const float*)d_in[2];
    float* out = (float*)d_out;

    const int N = in_sizes[0] / 3;

    dim3 tg(PLANE_ELEMS / 64, 3);
    transpose_kernel<<<tg, 256>>>(grid);

    constexpr int PAIRS = 8;                       // 16 points per warp
    const int pts_per_warp = 2 * PAIRS;
    const int warps = (N + pts_per_warp - 1) / pts_per_warp;
    const int blocks = (warps * 32 + 255) / 256;
    freqgrid_kernel<PAIRS><<<blocks, 256>>>(coords, freqs, out, N);
}

// round 14
// speedup vs baseline: 1.1203x; 1.1203x over previous
#include <cuda_runtime.h>
#include <cuda_fp16.h>

// FreqGrid triplane encoder. R14 = R12 (best: 70.1us) + smem-staged per-point
// scalars:
//  - threads 0..127 of each block compute (pt0,pt1,pt2,kd0,kd1,kd2) for the
//    block's 128 points once into shared memory; the gather loop reads them
//    back with 2 broadcast LDS.128 instead of 6 LDG.32 + 6 FFMA per iteration.
//  - everything else identical to R12: fp16 transposed grid (48 MB,
//    L2-resident), padded grid, half-warp per point, 2-stage plane pipeline,
//    HFMA2 blend, PAIRS=8, __ldcs/__stcs streaming hints.

#define RR 256
#define CHN 128
#define PLANE_ELEMS (RR * RR)              // 65536
#define GT_ELEMS (3 * PLANE_ELEMS * CHN)   // 48 MB of halfs
#define GT_PAD (33024)                     // covers +row+texel overrun (zeroed)

__device__ __half g_grid_t[GT_ELEMS + GT_PAD];

#define PI_OVER_R 0.01227184630308513f     // pi/256
#define KC        0.006135923151542565f    // pi/512

// swizzled half-index for (spatial row s, channel ch) in a 64x128 tile
__device__ __forceinline__ int sw_idx(int s, int ch) {
    int chunk = (ch >> 3) ^ ((s >> 2) & 15);
    return s * 128 + (chunk << 3) + (ch & 7);
}

// ---------------------------------------------------------------------------
// Transpose + quantize: in[p][ch][s] -> g_grid_t[p][s][ch] (fp16)
// ---------------------------------------------------------------------------
__global__ void __launch_bounds__(256) transpose_kernel(const float* __restrict__ g) {
    __shared__ __half tile[64 * 128];
    const int p  = blockIdx.y;
    const int s0 = blockIdx.x << 6;
    const int tid = threadIdx.x;

    const float* in = g + (size_t)p * CHN * PLANE_ELEMS + s0;

    #pragma unroll
    for (int i = 0; i < 8; i++) {
        int u  = i * 256 + tid;
        int q  = u & 15;
        int ch = u >> 4;
        float4 f = __ldcs((const float4*)(in + (size_t)ch * PLANE_ELEMS + 4 * q));
        tile[sw_idx(4 * q + 0, ch)] = __float2half_rn(f.x);
        tile[sw_idx(4 * q + 1, ch)] = __float2half_rn(f.y);
        tile[sw_idx(4 * q + 2, ch)] = __float2half_rn(f.z);
        tile[sw_idx(4 * q + 3, ch)] = __float2half_rn(f.w);
    }
    __syncthreads();

    __half* outp = g_grid_t + (size_t)p * PLANE_ELEMS * CHN + (size_t)s0 * CHN;
    #pragma unroll
    for (int i = 0; i < 4; i++) {
        int u  = i * 256 + tid;
        int c8 = u & 15;
        int s  = u >> 4;
        int chunk = c8 ^ ((s >> 2) & 15);
        uint4 val = *(const uint4*)&tile[s * 128 + (chunk << 3)];
        *(uint4*)(outp + s * CHN + 8 * c8) = val;
    }
}

// ---------------------------------------------------------------------------
// Gather + basis: half-warp per point, lane owns output channel c = lane&15
// ---------------------------------------------------------------------------
__device__ __forceinline__ void load_corners(const uint4* __restrict__ gb,
                                             int off, uint4* v) {
    v[0] = __ldg(&gb[off]);
    v[1] = __ldg(&gb[off + 16]);       // +x texel
    v[2] = __ldg(&gb[off + 4096]);     // +y row
    v[3] = __ldg(&gb[off + 4112]);
}

__device__ __forceinline__ void blend_plane(const uint4* v, float wxd, float wyd,
                                            float kdd, const float* frh,
                                            float& acc0, float& acc1) {
    __half2 w00 = __float2half2_rn((1.0f - wxd) * (1.0f - wyd));
    __half2 w01 = __float2half2_rn(wxd * (1.0f - wyd));
    __half2 w10 = __float2half2_rn((1.0f - wxd) * wyd);
    __half2 w11 = __float2half2_rn(wxd * wyd);

    const __half2* c0 = (const __half2*)&v[0];
    const __half2* c1 = (const __half2*)&v[1];
    const __half2* c2 = (const __half2*)&v[2];
    const __half2* c3 = (const __half2*)&v[3];

    #pragma unroll
    for (int q = 0; q < 4; q++) {
        __half2 cf = __hmul2(w00, c0[q]);
        cf = __hfma2(w01, c1[q], cf);
        cf = __hfma2(w10, c2[q], cf);
        cf = __hfma2(w11, c3[q], cf);
        float2 f = __half22float2(cf);
        acc0 = fmaf(f.x, __cosf(kdd * frh[2 * q]),     acc0);
        acc1 = fmaf(f.y, __cosf(kdd * frh[2 * q + 1]), acc1);
    }
}

template <int PAIRS>
__global__ void __launch_bounds__(256)
freqgrid_kernel(const float* __restrict__ coords,
                const float* __restrict__ freqs,
                float* __restrict__ out, int N) {
    // Per-block staging of per-point scalars: 128 points x {pt.xyz, kd.xyz}
    // stored as two float4s per point (32B stride, broadcast-friendly).
    __shared__ float4 s_pt[128 * 2];

    const int tid  = threadIdx.x;
    const int lane = tid & 31;
    const int sub  = lane >> 4;     // 0: point A, 1: point B
    const int cl   = lane & 15;     // output channel / uint4 slot
    const int wloc = tid >> 5;      // warp index within block (0..7)

    const int PTS_PER_WARP = 2 * PAIRS;                 // 16
    const int pbase = blockIdx.x * (8 * PTS_PER_WARP);  // block's first point

    if (tid < 128) {
        int n = min(pbase + tid, N - 1);
        float c0 = __ldcs(&coords[3 * n + 0]);
        float c1 = __ldcs(&coords[3 * n + 1]);
        float c2 = __ldcs(&coords[3 * n + 2]);
        float p0 = fmaf(c0, 127.5f, 127.5f);
        float p1 = fmaf(c1, 127.5f, 127.5f);
        float p2 = fmaf(c2, 127.5f, 127.5f);
        s_pt[2 * tid]     = make_float4(p0, p1, p2, 0.0f);
        s_pt[2 * tid + 1] = make_float4(fmaf(p0, PI_OVER_R, KC),
                                        fmaf(p1, PI_OVER_R, KC),
                                        fmaf(p2, PI_OVER_R, KC), 0.0f);
    }

    // Per-lane frequency constants for channels 8*cl + j
    float frh[8];
    #pragma unroll
    for (int j = 0; j < 8; j++) {
        float fq = __ldg(&freqs[8 * cl + j]);
        fq = fminf(fmaxf(fq, 0.0f), 1.0f);
        frh[j] = exp2f(fq * 8.0f) - 0.5f;
    }

    __syncthreads();

    const uint4* __restrict__ gb = (const uint4*)g_grid_t;   // texel = 16 uint4
    const int base0 = (blockIdx.x * 8 + wloc) * PTS_PER_WARP;

    #pragma unroll
    for (int t = 0; t < PAIRS; t++) {
        const int nb = base0 + 2 * t;
        if (nb >= N) return;
        const int n = min(nb + sub, N - 1);

        const int local = wloc * PTS_PER_WARP + 2 * t + sub;   // 0..127
        float4 P = s_pt[2 * local];
        float4 K = s_pt[2 * local + 1];
        float pt0 = P.x, pt1 = P.y, pt2 = P.z;
        float kd0 = K.x, kd1 = K.y, kd2 = K.z;

        // plane d samples (ix,iy) from pt[{1,0,0}], pt[{2,2,1}]
        // coords in [-1,1): top-edge corners carry exactly-zero weights;
        // padded grid makes the unclamped reads safe.
        int x0a = (int)pt1, y0a = (int)pt2;        // plane 0
        int x0b = (int)pt0, y0b = (int)pt2;        // plane 1
        int x0c = (int)pt0, y0c = (int)pt1;        // plane 2

        float wxa = pt1 - (float)x0a, wya = pt2 - (float)y0a;
        float wxb = pt0 - (float)x0b, wyb = pt2 - (float)y0b;
        float wxc = pt0 - (float)x0c, wyc = pt1 - (float)y0c;

        int offa = (((y0a << 8) + x0a) << 4) + cl;
        int offb = ((PLANE_ELEMS + (y0b << 8) + x0b) << 4) + cl;
        int offc = ((2 * PLANE_ELEMS + (y0c << 8) + x0c) << 4) + cl;

        float acc0 = 0.0f, acc1 = 0.0f;
        uint4 va[4], vb[4];

        // 2-deep software pipeline over the 3 planes
        load_corners(gb, offa, va);
        load_corners(gb, offb, vb);
        blend_plane(va, wxa, wya, kd0, frh, acc0, acc1);
        load_corners(gb, offc, va);
        blend_plane(vb, wxb, wyb, kd1, frh, acc0, acc1);
        blend_plane(va, wxc, wyc, kd2, frh, acc0, acc1);

        if (nb + sub < N) {
            __stcs(&out[n * 16 + cl], 2.0f * (acc0 + acc1));
        }
    }
}

// ---------------------------------------------------------------------------
// Harness entry
// ---------------------------------------------------------------------------
extern "C" void kernel_launch(void* const* d_in, const int* in_sizes, int n_in,
                              void* d_out, int out_size) {
    const float* coords = (const float*)d_in[0];
    const float* grid   = (const float*)d_in[1];
    const float* freqs  = (const float*)d_in[2];
    float* out = (float*)d_out;

    const int N = in_sizes[0] / 3;

    dim3 tg(PLANE_ELEMS / 64, 3);
    transpose_kernel<<<tg, 256>>>(grid);

    constexpr int PAIRS = 8;                       // 16 points per warp
    const int pts_per_warp = 2 * PAIRS;
    const int pts_per_block = 8 * pts_per_warp;    // 128
    const int blocks = (N + pts_per_block - 1) / pts_per_block;
    freqgrid_kernel<PAIRS><<<blocks, 256>>>(coords, freqs, out, N);
}